// round 6
// baseline (speedup 1.0000x reference)
#include <cuda_runtime.h>
#include <cstdint>

// ---------------- problem constants ----------------
#define BATCH 8192
#define INSZ  1024
#define HID   2048
#define NG    6144            // 3*HID
#define KTOT  3072            // INSZ + HID
#define KITERS 96
#define STAGES 3

// CTA tile 128(M) x 128(N), warp tile 64x64, 4 warps (2x2), 2 CTAs/SM
#define STAGE_FLOATS 8192      // A 128x32 (4096) + B 128x32 (4096)
#define STAGE_BYTES  32768
#define SMEM_TOTAL (STAGES * STAGE_BYTES)   // 98304 per CTA

// scratch (static device arrays are allowed)
__device__ float g_BT[(size_t)NG * KTOT];          // [W;Wh]^T K-major, tf32-rounded
__device__ float g_gates[(size_t)BATCH * NG];      // gate pre-activations

// ---------------- ptx helpers ----------------
#define CP_ASYNC16(dst, src) \
    asm volatile("cp.async.cg.shared.global [%0], [%1], 16;" :: "r"(dst), "l"(src))
#define CP_COMMIT() asm volatile("cp.async.commit_group;" ::: "memory")
#define CP_WAIT2()  asm volatile("cp.async.wait_group 2;" ::: "memory")

#define LDSM4(r0, r1, r2, r3, addr) \
    asm volatile("ldmatrix.sync.aligned.m8n8.x4.shared.b16 {%0,%1,%2,%3}, [%4];" \
        : "=r"(r0), "=r"(r1), "=r"(r2), "=r"(r3) : "r"(addr))

#define MMA_TF32(d, a, b) \
    asm volatile("mma.sync.aligned.m16n8k8.row.col.f32.tf32.tf32.f32 " \
        "{%0,%1,%2,%3}, {%4,%5,%6,%7}, {%8,%9}, {%0,%1,%2,%3};" \
        : "+f"((d)[0]), "+f"((d)[1]), "+f"((d)[2]), "+f"((d)[3]) \
        : "r"((a)[0]), "r"((a)[1]), "r"((a)[2]), "r"((a)[3]), \
          "r"((b)[0]), "r"((b)[1]))

// ---------------- kernel 1: pack [W; Wh] -> BT[n][k] (K-major, tf32-rounded) ----------------
__global__ void __launch_bounds__(256) lstm_pack_bt(
    const float* __restrict__ W, const float* __restrict__ Wh, float* __restrict__ BT) {
    __shared__ float s[32 * 129];
    const int tid = threadIdx.x;
    const int k0 = blockIdx.x * 32, n0 = blockIdx.y * 128;

    #pragma unroll
    for (int i = 0; i < 4; i++) {
        int idx = tid + i * 256;
        int r = idx >> 5;
        int c4 = idx & 31;
        int k = k0 + r;
        const float* src = (k < INSZ) ? (W + (size_t)k * NG + n0 + c4 * 4)
                                      : (Wh + (size_t)(k - INSZ) * NG + n0 + c4 * 4);
        float4 v = *(const float4*)src;
        uint32_t rr;
        asm("cvt.rna.tf32.f32 %0, %1;" : "=r"(rr) : "f"(v.x)); v.x = __uint_as_float(rr);
        asm("cvt.rna.tf32.f32 %0, %1;" : "=r"(rr) : "f"(v.y)); v.y = __uint_as_float(rr);
        asm("cvt.rna.tf32.f32 %0, %1;" : "=r"(rr) : "f"(v.z)); v.z = __uint_as_float(rr);
        asm("cvt.rna.tf32.f32 %0, %1;" : "=r"(rr) : "f"(v.w)); v.w = __uint_as_float(rr);
        s[r * 129 + c4 * 4 + 0] = v.x;
        s[r * 129 + c4 * 4 + 1] = v.y;
        s[r * 129 + c4 * 4 + 2] = v.z;
        s[r * 129 + c4 * 4 + 3] = v.w;
    }
    __syncthreads();
    #pragma unroll
    for (int i = 0; i < 4; i++) {
        int idx = tid + i * 256;
        int n = idx >> 3;
        int kg = idx & 7;
        float4 v;
        v.x = s[(kg * 4 + 0) * 129 + n];
        v.y = s[(kg * 4 + 1) * 129 + n];
        v.z = s[(kg * 4 + 2) * 129 + n];
        v.w = s[(kg * 4 + 3) * 129 + n];
        *(float4*)(BT + (size_t)(n0 + n) * KTOT + k0 + kg * 4) = v;
    }
}

// ---------------- kernel 2: tf32 mma.sync GEMM, 2 CTAs/SM, issue-before-wait pipeline ----------------
__global__ void __launch_bounds__(128, 2) lstm_gemm(
    const float* __restrict__ X, const float* __restrict__ H,
    const float* __restrict__ BT, float* __restrict__ gates) {
    extern __shared__ float smem[];
    const int tid = threadIdx.x;
    const int lane = tid & 31, wid = tid >> 5;
    const int wm = wid & 1, wn = wid >> 1;            // 2x2 warp grid, warp tile 64x64
    const int m0 = blockIdx.y * 128, n0 = blockIdx.x * 128;

    const uint32_t sbase = (uint32_t)__cvta_generic_to_shared(smem);

    float acc[4][8][4];
    #pragma unroll
    for (int i = 0; i < 4; i++)
        #pragma unroll
        for (int j = 0; j < 8; j++)
            #pragma unroll
            for (int k = 0; k < 4; k++) acc[i][j][k] = 0.f;

    const int a_moff = ((lane >> 3) & 1) * 8 + (lane & 7);
    const int a_csel = lane >> 4;
    const int b_noff = ((lane >> 4) & 1) * 8 + (lane & 7);
    const int b_csel = (lane >> 3) & 1;

    auto load_stage = [&](int kc, int s) {
        float* As = smem + s * STAGE_FLOATS;
        float* Bs = As + 4096;
        const float* aptr;
        int lda, acol;
        if (kc < INSZ / 32) { aptr = X; lda = INSZ; acol = kc * 32; }
        else                { aptr = H; lda = HID;  acol = (kc - INSZ / 32) * 32; }
        #pragma unroll
        for (int i = 0; i < 8; i++) {
            int ch = tid + i * 128;                    // 0..1023
            int m = ch >> 3, c = ch & 7;
            const float* src = aptr + (size_t)(m0 + m) * lda + acol + c * 4;
            uint32_t dst = (uint32_t)__cvta_generic_to_shared(As + m * 32 + ((c ^ (m & 7)) << 2));
            CP_ASYNC16(dst, src);
        }
        #pragma unroll
        for (int i = 0; i < 8; i++) {
            int ch = tid + i * 128;
            int n = ch >> 3, c = ch & 7;
            const float* src = BT + (size_t)(n0 + n) * KTOT + kc * 32 + c * 4;
            uint32_t dst = (uint32_t)__cvta_generic_to_shared(Bs + n * 32 + ((c ^ (n & 7)) << 2));
            CP_ASYNC16(dst, src);
        }
    };

    auto load_afrag = [&](uint32_t As, int kk, uint32_t a[4][4]) {
        #pragma unroll
        for (int mb = 0; mb < 4; mb++) {
            int m = wm * 64 + mb * 16 + a_moff;
            int c = kk * 2 + a_csel;
            uint32_t addr = As + m * 128 + ((c ^ (m & 7)) << 4);
            LDSM4(a[mb][0], a[mb][1], a[mb][2], a[mb][3], addr);
        }
    };
    auto load_bfrag = [&](uint32_t Bs, int kk, uint32_t b[8][2]) {
        #pragma unroll
        for (int p = 0; p < 4; p++) {
            int n = wn * 64 + p * 16 + b_noff;
            int c = kk * 2 + b_csel;
            uint32_t addr = Bs + n * 128 + ((c ^ (n & 7)) << 4);
            LDSM4(b[2 * p][0], b[2 * p][1], b[2 * p + 1][0], b[2 * p + 1][1], addr);
        }
    };

    // prologue: fill 2 of 3 stages
    #pragma unroll
    for (int s = 0; s < STAGES - 1; s++) { load_stage(s, s); CP_COMMIT(); }

    uint32_t afr[2][4][4], bfr[2][8][2];

    for (int kc = 0; kc < KITERS; kc++) {
        // slot (kc+2)%3 was consumed in iteration kc-1; guard with barrier
        __syncthreads();
        int ls = kc + STAGES - 1;
        if (ls < KITERS) load_stage(ls, ls % STAGES);
        CP_COMMIT();
        CP_WAIT2();                 // kc's group done; kc+1, kc+2 may be in flight
        __syncthreads();            // cross-thread visibility of stage kc

        const uint32_t As = sbase + (kc % STAGES) * STAGE_BYTES;
        const uint32_t Bs = As + 16384;

        load_afrag(As, 0, afr[0]);
        load_bfrag(Bs, 0, bfr[0]);
        #pragma unroll
        for (int kk = 0; kk < 4; kk++) {
            int cur = kk & 1, nxt = cur ^ 1;
            if (kk < 3) {
                load_afrag(As, kk + 1, afr[nxt]);
                load_bfrag(Bs, kk + 1, bfr[nxt]);
            }
            #pragma unroll
            for (int mb = 0; mb < 4; mb++)
                #pragma unroll
                for (int nb = 0; nb < 8; nb++)
                    MMA_TF32(acc[mb][nb], afr[cur][mb], bfr[cur][nb]);
        }
    }

    // write accumulators to gates scratch
    const int g = lane >> 2, tig = lane & 3;
    #pragma unroll
    for (int mb = 0; mb < 4; mb++) {
        #pragma unroll
        for (int nb = 0; nb < 8; nb++) {
            int row = m0 + wm * 64 + mb * 16 + g;
            int col = n0 + wn * 64 + nb * 8 + tig * 2;
            *(float2*)(gates + (size_t)row * NG + col) =
                make_float2(acc[mb][nb][0], acc[mb][nb][1]);
            *(float2*)(gates + (size_t)(row + 8) * NG + col) =
                make_float2(acc[mb][nb][2], acc[mb][nb][3]);
        }
    }
}

// ---------------- kernel 3: LSTM epilogue ----------------
__device__ __forceinline__ float fast_sigmoid(float x) {
    return __fdividef(1.f, 1.f + __expf(-x));
}
__device__ __forceinline__ float fast_tanh(float x) {
    return __fdividef(2.f, 1.f + __expf(-2.f * x)) - 1.f;
}

__global__ void lstm_epilogue(const float* __restrict__ gates, const float* __restrict__ c0,
                              const float* __restrict__ bias, float* __restrict__ out) {
    int t = blockIdx.x * blockDim.x + threadIdx.x;
    int n = (t & 511) * 4;
    int m = t >> 9;
    const float4 f4 = *(const float4*)(gates + (size_t)m * NG + n);
    const float4 i4 = *(const float4*)(gates + (size_t)m * NG + HID + n);
    const float4 g4 = *(const float4*)(gates + (size_t)m * NG + 2 * HID + n);
    const float4 c4 = *(const float4*)(c0 + (size_t)m * HID + n);
    const float4 bf = *(const float4*)(bias + n);
    const float4 bi = *(const float4*)(bias + HID + n);
    const float4 bc = *(const float4*)(bias + 2 * HID + n);
    float4 o;
    o.x = fast_sigmoid(f4.x + bf.x) * c4.x + fast_sigmoid(i4.x + bi.x) * fast_tanh(g4.x + bc.x);
    o.y = fast_sigmoid(f4.y + bf.y) * c4.y + fast_sigmoid(i4.y + bi.y) * fast_tanh(g4.y + bc.y);
    o.z = fast_sigmoid(f4.z + bf.z) * c4.z + fast_sigmoid(i4.z + bi.z) * fast_tanh(g4.z + bc.z);
    o.w = fast_sigmoid(f4.w + bf.w) * c4.w + fast_sigmoid(i4.w + bi.w) * fast_tanh(g4.w + bc.w);
    *(float4*)(out + (size_t)m * HID + n) = o;
}

// ---------------- host launch ----------------
extern "C" void kernel_launch(void* const* d_in, const int* in_sizes, int n_in,
                              void* d_out, int out_size) {
    const float* X    = (const float*)d_in[0];
    const float* H0   = (const float*)d_in[1];
    const float* C0   = (const float*)d_in[2];
    const float* W    = (const float*)d_in[3];
    const float* Wh   = (const float*)d_in[4];
    const float* Bias = (const float*)d_in[5];
    float* out = (float*)d_out;

    float* bt = nullptr;
    float* gates = nullptr;
    cudaGetSymbolAddress((void**)&bt, g_BT);
    cudaGetSymbolAddress((void**)&gates, g_gates);

    cudaFuncSetAttribute(lstm_gemm, cudaFuncAttributeMaxDynamicSharedMemorySize, SMEM_TOTAL);

    lstm_pack_bt<<<dim3(KTOT / 32, NG / 128), 256>>>(W, Wh, bt);
    lstm_gemm<<<dim3(NG / 128, BATCH / 128), 128, SMEM_TOTAL>>>(X, H0, bt, gates);
    lstm_epilogue<<<(BATCH * HID / 4) / 256, 256>>>(gates, C0, Bias, out);
}

// round 7
// speedup vs baseline: 1.9258x; 1.9258x over previous
#include <cuda_runtime.h>
#include <cuda_fp16.h>
#include <cstdint>

// ---------------- problem constants ----------------
#define BATCH 8192
#define INSZ  1024
#define HID   2048
#define NG    6144            // 3*HID
#define KTOT  3072            // INSZ + HID
#define KITERS 48             // K-chunks of 64 halfs
#define STAGES 3

// CTA tile 128(M) x 128(N), warp tile 64x64, 4 warps (2x2), 2 CTAs/SM
// stage: A 128x64 half (16KB) + B 128x64 half (16KB)
#define STAGE_BYTES  32768
#define SMEM_TOTAL (STAGES * STAGE_BYTES)   // 98304 per CTA

// scratch (static device arrays are allowed)
__device__ __half g_BT[(size_t)NG * KTOT];       // [W;Wh]^T K-major, half
__device__ __half g_AH[(size_t)BATCH * KTOT];    // [X|H] merged, half
__device__ float  g_gates[(size_t)BATCH * NG];   // gate pre-activations

// ---------------- ptx helpers ----------------
#define CP_ASYNC16(dst, src) \
    asm volatile("cp.async.cg.shared.global [%0], [%1], 16;" :: "r"(dst), "l"(src))
#define CP_COMMIT() asm volatile("cp.async.commit_group;" ::: "memory")
#define CP_WAIT1()  asm volatile("cp.async.wait_group 1;" ::: "memory")

#define LDSM4(r0, r1, r2, r3, addr) \
    asm volatile("ldmatrix.sync.aligned.m8n8.x4.shared.b16 {%0,%1,%2,%3}, [%4];" \
        : "=r"(r0), "=r"(r1), "=r"(r2), "=r"(r3) : "r"(addr))

#define MMA_F16(d, a, b) \
    asm volatile("mma.sync.aligned.m16n8k16.row.col.f32.f16.f16.f32 " \
        "{%0,%1,%2,%3}, {%4,%5,%6,%7}, {%8,%9}, {%0,%1,%2,%3};" \
        : "+f"((d)[0]), "+f"((d)[1]), "+f"((d)[2]), "+f"((d)[3]) \
        : "r"((a)[0]), "r"((a)[1]), "r"((a)[2]), "r"((a)[3]), \
          "r"((b)[0]), "r"((b)[1]))

// ---------------- kernel 1: pack [W; Wh] -> BT[n][k] (K-major, half) ----------------
__global__ void __launch_bounds__(256) lstm_pack_bt(
    const float* __restrict__ W, const float* __restrict__ Wh, __half* __restrict__ BT) {
    __shared__ float s[32 * 129];
    const int tid = threadIdx.x;
    const int k0 = blockIdx.x * 32, n0 = blockIdx.y * 128;

    #pragma unroll
    for (int i = 0; i < 4; i++) {
        int idx = tid + i * 256;
        int r = idx >> 5;                 // k row 0..31
        int c4 = idx & 31;                // float4 col
        int k = k0 + r;
        const float* src = (k < INSZ) ? (W + (size_t)k * NG + n0 + c4 * 4)
                                      : (Wh + (size_t)(k - INSZ) * NG + n0 + c4 * 4);
        float4 v = *(const float4*)src;
        s[r * 129 + c4 * 4 + 0] = v.x;
        s[r * 129 + c4 * 4 + 1] = v.y;
        s[r * 129 + c4 * 4 + 2] = v.z;
        s[r * 129 + c4 * 4 + 3] = v.w;
    }
    __syncthreads();
    #pragma unroll
    for (int i = 0; i < 4; i++) {
        int idx = tid + i * 256;
        int n = idx >> 3;                 // 0..127
        int kg = idx & 7;                 // group of 4 k
        __half2 p0 = __floats2half2_rn(s[(kg * 4 + 0) * 129 + n], s[(kg * 4 + 1) * 129 + n]);
        __half2 p1 = __floats2half2_rn(s[(kg * 4 + 2) * 129 + n], s[(kg * 4 + 3) * 129 + n]);
        uint2 u;
        u.x = *reinterpret_cast<uint32_t*>(&p0);
        u.y = *reinterpret_cast<uint32_t*>(&p1);
        *(uint2*)(BT + (size_t)(n0 + n) * KTOT + k0 + kg * 4) = u;
    }
}

// ---------------- kernel 1b: convert [X|H] -> AH half ----------------
__global__ void __launch_bounds__(256) lstm_cvt_ah(
    const float* __restrict__ X, const float* __restrict__ H, __half* __restrict__ AH) {
    int t = blockIdx.x * blockDim.x + threadIdx.x;     // one 8-elem group
    int m = t / (KTOT / 8);
    int col = (t % (KTOT / 8)) * 8;
    const float* src = (col < INSZ) ? (X + (size_t)m * INSZ + col)
                                    : (H + (size_t)m * HID + (col - INSZ));
    float4 v0 = ((const float4*)src)[0];
    float4 v1 = ((const float4*)src)[1];
    __half2 h0 = __floats2half2_rn(v0.x, v0.y);
    __half2 h1 = __floats2half2_rn(v0.z, v0.w);
    __half2 h2 = __floats2half2_rn(v1.x, v1.y);
    __half2 h3 = __floats2half2_rn(v1.z, v1.w);
    uint4 u;
    u.x = *reinterpret_cast<uint32_t*>(&h0);
    u.y = *reinterpret_cast<uint32_t*>(&h1);
    u.z = *reinterpret_cast<uint32_t*>(&h2);
    u.w = *reinterpret_cast<uint32_t*>(&h3);
    *(uint4*)(AH + (size_t)m * KTOT + col) = u;
}

// ---------------- kernel 2: fp16 mma.sync GEMM, 2 CTAs/SM ----------------
__global__ void __launch_bounds__(128, 2) lstm_gemm(
    const __half* __restrict__ AH, const __half* __restrict__ BT,
    float* __restrict__ gates) {
    extern __shared__ char smem[];
    const int tid = threadIdx.x;
    const int lane = tid & 31, wid = tid >> 5;
    const int wm = wid & 1, wn = wid >> 1;            // 2x2 warp grid, warp tile 64x64
    const int m0 = blockIdx.y * 128, n0 = blockIdx.x * 128;

    const uint32_t sbase = (uint32_t)__cvta_generic_to_shared(smem);

    float acc[4][8][4];
    #pragma unroll
    for (int i = 0; i < 4; i++)
        #pragma unroll
        for (int j = 0; j < 8; j++)
            #pragma unroll
            for (int k = 0; k < 4; k++) acc[i][j][k] = 0.f;

    const int a_moff = ((lane >> 3) & 1) * 8 + (lane & 7);
    const int a_csel = lane >> 4;
    const int b_noff = ((lane >> 4) & 1) * 8 + (lane & 7);
    const int b_csel = (lane >> 3) & 1;

    // stage layout: A 128 rows x 128B, then B 128 rows x 128B
    auto load_stage = [&](int kc, int s) {
        const uint32_t As = sbase + s * STAGE_BYTES;
        const uint32_t Bs = As + 16384;
        #pragma unroll
        for (int i = 0; i < 8; i++) {
            int ch = tid + i * 128;                    // 0..1023
            int m = ch >> 3, c = ch & 7;               // c: 16B chunk (8 halfs)
            const __half* src = AH + (size_t)(m0 + m) * KTOT + kc * 64 + c * 8;
            uint32_t dst = As + m * 128 + ((c ^ (m & 7)) << 4);
            CP_ASYNC16(dst, src);
        }
        #pragma unroll
        for (int i = 0; i < 8; i++) {
            int ch = tid + i * 128;
            int n = ch >> 3, c = ch & 7;
            const __half* src = BT + (size_t)(n0 + n) * KTOT + kc * 64 + c * 8;
            uint32_t dst = Bs + n * 128 + ((c ^ (n & 7)) << 4);
            CP_ASYNC16(dst, src);
        }
    };

    auto load_afrag = [&](uint32_t As, int kk, uint32_t a[4][4]) {
        #pragma unroll
        for (int mb = 0; mb < 4; mb++) {
            int m = wm * 64 + mb * 16 + a_moff;
            int c = kk * 2 + a_csel;
            uint32_t addr = As + m * 128 + ((c ^ (m & 7)) << 4);
            LDSM4(a[mb][0], a[mb][1], a[mb][2], a[mb][3], addr);
        }
    };
    auto load_bfrag = [&](uint32_t Bs, int kk, uint32_t b[8][2]) {
        #pragma unroll
        for (int p = 0; p < 4; p++) {
            int n = wn * 64 + p * 16 + b_noff;
            int c = kk * 2 + b_csel;
            uint32_t addr = Bs + n * 128 + ((c ^ (n & 7)) << 4);
            LDSM4(b[2 * p][0], b[2 * p][1], b[2 * p + 1][0], b[2 * p + 1][1], addr);
        }
    };

    // prologue: fill 2 of 3 stages
    #pragma unroll
    for (int s = 0; s < STAGES - 1; s++) { load_stage(s, s); CP_COMMIT(); }

    uint32_t afr[2][4][4], bfr[2][8][2];

    for (int kc = 0; kc < KITERS; kc++) {
        CP_WAIT1();
        __syncthreads();
        int ls = kc + STAGES - 1;
        if (ls < KITERS) load_stage(ls, ls % STAGES);
        CP_COMMIT();

        const uint32_t As = sbase + (kc % STAGES) * STAGE_BYTES;
        const uint32_t Bs = As + 16384;

        load_afrag(As, 0, afr[0]);
        load_bfrag(Bs, 0, bfr[0]);
        #pragma unroll
        for (int kk = 0; kk < 4; kk++) {                // 4 x k16 per 64-chunk
            int cur = kk & 1, nxt = cur ^ 1;
            if (kk < 3) {
                load_afrag(As, kk + 1, afr[nxt]);
                load_bfrag(Bs, kk + 1, bfr[nxt]);
            }
            #pragma unroll
            for (int mb = 0; mb < 4; mb++)
                #pragma unroll
                for (int nb = 0; nb < 8; nb++)
                    MMA_F16(acc[mb][nb], afr[cur][mb], bfr[cur][nb]);
        }
    }

    // write accumulators to gates scratch
    const int g = lane >> 2, tig = lane & 3;
    #pragma unroll
    for (int mb = 0; mb < 4; mb++) {
        #pragma unroll
        for (int nb = 0; nb < 8; nb++) {
            int row = m0 + wm * 64 + mb * 16 + g;
            int col = n0 + wn * 64 + nb * 8 + tig * 2;
            *(float2*)(gates + (size_t)row * NG + col) =
                make_float2(acc[mb][nb][0], acc[mb][nb][1]);
            *(float2*)(gates + (size_t)(row + 8) * NG + col) =
                make_float2(acc[mb][nb][2], acc[mb][nb][3]);
        }
    }
}

// ---------------- kernel 3: LSTM epilogue ----------------
__device__ __forceinline__ float fast_sigmoid(float x) {
    return __fdividef(1.f, 1.f + __expf(-x));
}
__device__ __forceinline__ float fast_tanh(float x) {
    return __fdividef(2.f, 1.f + __expf(-2.f * x)) - 1.f;
}

__global__ void lstm_epilogue(const float* __restrict__ gates, const float* __restrict__ c0,
                              const float* __restrict__ bias, float* __restrict__ out) {
    int t = blockIdx.x * blockDim.x + threadIdx.x;
    int n = (t & 511) * 4;
    int m = t >> 9;
    const float4 f4 = *(const float4*)(gates + (size_t)m * NG + n);
    const float4 i4 = *(const float4*)(gates + (size_t)m * NG + HID + n);
    const float4 g4 = *(const float4*)(gates + (size_t)m * NG + 2 * HID + n);
    const float4 c4 = *(const float4*)(c0 + (size_t)m * HID + n);
    const float4 bf = *(const float4*)(bias + n);
    const float4 bi = *(const float4*)(bias + HID + n);
    const float4 bc = *(const float4*)(bias + 2 * HID + n);
    float4 o;
    o.x = fast_sigmoid(f4.x + bf.x) * c4.x + fast_sigmoid(i4.x + bi.x) * fast_tanh(g4.x + bc.x);
    o.y = fast_sigmoid(f4.y + bf.y) * c4.y + fast_sigmoid(i4.y + bi.y) * fast_tanh(g4.y + bc.y);
    o.z = fast_sigmoid(f4.z + bf.z) * c4.z + fast_sigmoid(i4.z + bi.z) * fast_tanh(g4.z + bc.z);
    o.w = fast_sigmoid(f4.w + bf.w) * c4.w + fast_sigmoid(i4.w + bi.w) * fast_tanh(g4.w + bc.w);
    *(float4*)(out + (size_t)m * HID + n) = o;
}

// ---------------- host launch ----------------
extern "C" void kernel_launch(void* const* d_in, const int* in_sizes, int n_in,
                              void* d_out, int out_size) {
    const float* X    = (const float*)d_in[0];
    const float* H0   = (const float*)d_in[1];
    const float* C0   = (const float*)d_in[2];
    const float* W    = (const float*)d_in[3];
    const float* Wh   = (const float*)d_in[4];
    const float* Bias = (const float*)d_in[5];
    float* out = (float*)d_out;

    __half* bt = nullptr;
    __half* ah = nullptr;
    float* gates = nullptr;
    cudaGetSymbolAddress((void**)&bt, g_BT);
    cudaGetSymbolAddress((void**)&ah, g_AH);
    cudaGetSymbolAddress((void**)&gates, g_gates);

    cudaFuncSetAttribute(lstm_gemm, cudaFuncAttributeMaxDynamicSharedMemorySize, SMEM_TOTAL);

    lstm_pack_bt<<<dim3(KTOT / 32, NG / 128), 256>>>(W, Wh, bt);
    lstm_cvt_ah<<<(BATCH * (KTOT / 8)) / 256, 256>>>(X, H0, ah);
    lstm_gemm<<<dim3(NG / 128, BATCH / 128), 128, SMEM_TOTAL>>>(ah, bt, gates);
    lstm_epilogue<<<(BATCH * HID / 4) / 256, 256>>>(gates, C0, Bias, out);
}

// round 8
// speedup vs baseline: 1.9574x; 1.0164x over previous
#include <cuda_runtime.h>
#include <cuda_fp16.h>
#include <cstdint>

// ---------------- problem constants ----------------
#define BATCH 8192
#define INSZ  1024
#define HID   2048
#define NG    6144            // 3*HID
#define KTOT  3072            // INSZ + HID
#define KITERS 48             // K-chunks of 64 halfs
#define STAGES 3

// CTA tile 128(M) x 128(N), warp tile 64x64, 4 warps (2x2), 2 CTAs/SM
#define STAGE_BYTES  32768
#define SMEM_TOTAL (STAGES * STAGE_BYTES)   // 98304 per CTA

// scratch (static device arrays are allowed)
__device__ __half g_BT[(size_t)NG * KTOT];       // [W;Wh]^T K-major, half
__device__ __half g_AH[(size_t)BATCH * KTOT];    // [X|H] merged, half
__device__ __half g_gates[(size_t)BATCH * NG];   // gate pre-activations (half)

// ---------------- ptx helpers ----------------
#define CP_ASYNC16(dst, src) \
    asm volatile("cp.async.cg.shared.global [%0], [%1], 16;" :: "r"(dst), "l"(src))
#define CP_COMMIT() asm volatile("cp.async.commit_group;" ::: "memory")
#define CP_WAIT1()  asm volatile("cp.async.wait_group 1;" ::: "memory")

#define LDSM4(r0, r1, r2, r3, addr) \
    asm volatile("ldmatrix.sync.aligned.m8n8.x4.shared.b16 {%0,%1,%2,%3}, [%4];" \
        : "=r"(r0), "=r"(r1), "=r"(r2), "=r"(r3) : "r"(addr))

#define MMA_F16(d, a, b) \
    asm volatile("mma.sync.aligned.m16n8k16.row.col.f32.f16.f16.f32 " \
        "{%0,%1,%2,%3}, {%4,%5,%6,%7}, {%8,%9}, {%0,%1,%2,%3};" \
        : "+f"((d)[0]), "+f"((d)[1]), "+f"((d)[2]), "+f"((d)[3]) \
        : "r"((a)[0]), "r"((a)[1]), "r"((a)[2]), "r"((a)[3]), \
          "r"((b)[0]), "r"((b)[1]))

// ---------------- kernel 1: pack [W; Wh] -> BT[n][k] (K-major, half) ----------------
__global__ void __launch_bounds__(256) lstm_pack_bt(
    const float* __restrict__ W, const float* __restrict__ Wh, __half* __restrict__ BT) {
    __shared__ float s[32 * 129];
    const int tid = threadIdx.x;
    const int k0 = blockIdx.x * 32, n0 = blockIdx.y * 128;

    #pragma unroll
    for (int i = 0; i < 4; i++) {
        int idx = tid + i * 256;
        int r = idx >> 5;
        int c4 = idx & 31;
        int k = k0 + r;
        const float* src = (k < INSZ) ? (W + (size_t)k * NG + n0 + c4 * 4)
                                      : (Wh + (size_t)(k - INSZ) * NG + n0 + c4 * 4);
        float4 v = *(const float4*)src;
        s[r * 129 + c4 * 4 + 0] = v.x;
        s[r * 129 + c4 * 4 + 1] = v.y;
        s[r * 129 + c4 * 4 + 2] = v.z;
        s[r * 129 + c4 * 4 + 3] = v.w;
    }
    __syncthreads();
    #pragma unroll
    for (int i = 0; i < 4; i++) {
        int idx = tid + i * 256;
        int n = idx >> 3;
        int kg = idx & 7;
        __half2 p0 = __floats2half2_rn(s[(kg * 4 + 0) * 129 + n], s[(kg * 4 + 1) * 129 + n]);
        __half2 p1 = __floats2half2_rn(s[(kg * 4 + 2) * 129 + n], s[(kg * 4 + 3) * 129 + n]);
        uint2 u;
        u.x = *reinterpret_cast<uint32_t*>(&p0);
        u.y = *reinterpret_cast<uint32_t*>(&p1);
        *(uint2*)(BT + (size_t)(n0 + n) * KTOT + k0 + kg * 4) = u;
    }
}

// ---------------- kernel 1b: convert [X|H] -> AH half ----------------
__global__ void __launch_bounds__(256) lstm_cvt_ah(
    const float* __restrict__ X, const float* __restrict__ H, __half* __restrict__ AH) {
    int t = blockIdx.x * blockDim.x + threadIdx.x;
    int m = t / (KTOT / 8);
    int col = (t % (KTOT / 8)) * 8;
    const float* src = (col < INSZ) ? (X + (size_t)m * INSZ + col)
                                    : (H + (size_t)m * HID + (col - INSZ));
    float4 v0 = ((const float4*)src)[0];
    float4 v1 = ((const float4*)src)[1];
    __half2 h0 = __floats2half2_rn(v0.x, v0.y);
    __half2 h1 = __floats2half2_rn(v0.z, v0.w);
    __half2 h2 = __floats2half2_rn(v1.x, v1.y);
    __half2 h3 = __floats2half2_rn(v1.z, v1.w);
    uint4 u;
    u.x = *reinterpret_cast<uint32_t*>(&h0);
    u.y = *reinterpret_cast<uint32_t*>(&h1);
    u.z = *reinterpret_cast<uint32_t*>(&h2);
    u.w = *reinterpret_cast<uint32_t*>(&h3);
    *(uint4*)(AH + (size_t)m * KTOT + col) = u;
}

// ---------------- kernel 2: fp16 mma.sync GEMM, 2 CTAs/SM ----------------
__global__ void __launch_bounds__(128, 2) lstm_gemm(
    const __half* __restrict__ AH, const __half* __restrict__ BT,
    __half* __restrict__ gates) {
    extern __shared__ char smem[];
    const int tid = threadIdx.x;
    const int lane = tid & 31, wid = tid >> 5;
    const int wm = wid & 1, wn = wid >> 1;            // 2x2 warp grid, warp tile 64x64
    const int m0 = blockIdx.y * 128, n0 = blockIdx.x * 128;

    const uint32_t sbase = (uint32_t)__cvta_generic_to_shared(smem);

    float acc[4][8][4];
    #pragma unroll
    for (int i = 0; i < 4; i++)
        #pragma unroll
        for (int j = 0; j < 8; j++)
            #pragma unroll
            for (int k = 0; k < 4; k++) acc[i][j][k] = 0.f;

    const int a_moff = ((lane >> 3) & 1) * 8 + (lane & 7);
    const int a_csel = lane >> 4;
    const int b_noff = ((lane >> 4) & 1) * 8 + (lane & 7);
    const int b_csel = (lane >> 3) & 1;

    auto load_stage = [&](int kc, int s) {
        const uint32_t As = sbase + s * STAGE_BYTES;
        const uint32_t Bs = As + 16384;
        #pragma unroll
        for (int i = 0; i < 8; i++) {
            int ch = tid + i * 128;
            int m = ch >> 3, c = ch & 7;
            const __half* src = AH + (size_t)(m0 + m) * KTOT + kc * 64 + c * 8;
            uint32_t dst = As + m * 128 + ((c ^ (m & 7)) << 4);
            CP_ASYNC16(dst, src);
        }
        #pragma unroll
        for (int i = 0; i < 8; i++) {
            int ch = tid + i * 128;
            int n = ch >> 3, c = ch & 7;
            const __half* src = BT + (size_t)(n0 + n) * KTOT + kc * 64 + c * 8;
            uint32_t dst = Bs + n * 128 + ((c ^ (n & 7)) << 4);
            CP_ASYNC16(dst, src);
        }
    };

    auto load_afrag = [&](uint32_t As, int kk, uint32_t a[4][4]) {
        #pragma unroll
        for (int mb = 0; mb < 4; mb++) {
            int m = wm * 64 + mb * 16 + a_moff;
            int c = kk * 2 + a_csel;
            uint32_t addr = As + m * 128 + ((c ^ (m & 7)) << 4);
            LDSM4(a[mb][0], a[mb][1], a[mb][2], a[mb][3], addr);
        }
    };
    auto load_bfrag = [&](uint32_t Bs, int kk, uint32_t b[8][2]) {
        #pragma unroll
        for (int p = 0; p < 4; p++) {
            int n = wn * 64 + p * 16 + b_noff;
            int c = kk * 2 + b_csel;
            uint32_t addr = Bs + n * 128 + ((c ^ (n & 7)) << 4);
            LDSM4(b[2 * p][0], b[2 * p][1], b[2 * p + 1][0], b[2 * p + 1][1], addr);
        }
    };

    // prologue: fill 2 of 3 stages
    #pragma unroll
    for (int s = 0; s < STAGES - 1; s++) { load_stage(s, s); CP_COMMIT(); }

    uint32_t afr[2][4][4], bfr[2][8][2];

    for (int kc = 0; kc < KITERS; kc++) {
        CP_WAIT1();
        __syncthreads();
        int ls = kc + STAGES - 1;
        if (ls < KITERS) load_stage(ls, ls % STAGES);
        CP_COMMIT();

        const uint32_t As = sbase + (kc % STAGES) * STAGE_BYTES;
        const uint32_t Bs = As + 16384;

        load_afrag(As, 0, afr[0]);
        load_bfrag(Bs, 0, bfr[0]);
        #pragma unroll
        for (int kk = 0; kk < 4; kk++) {
            int cur = kk & 1, nxt = cur ^ 1;
            if (kk < 3) {
                load_afrag(As, kk + 1, afr[nxt]);
                load_bfrag(Bs, kk + 1, bfr[nxt]);
            }
            #pragma unroll
            for (int mb = 0; mb < 4; mb++)
                #pragma unroll
                for (int nb = 0; nb < 8; nb++)
                    MMA_F16(acc[mb][nb], afr[cur][mb], bfr[cur][nb]);
        }
    }

    // write accumulators to gates scratch (fp16)
    const int g = lane >> 2, tig = lane & 3;
    #pragma unroll
    for (int mb = 0; mb < 4; mb++) {
        #pragma unroll
        for (int nb = 0; nb < 8; nb++) {
            int row = m0 + wm * 64 + mb * 16 + g;
            int col = n0 + wn * 64 + nb * 8 + tig * 2;
            *(__half2*)(gates + (size_t)row * NG + col) =
                __floats2half2_rn(acc[mb][nb][0], acc[mb][nb][1]);
            *(__half2*)(gates + (size_t)(row + 8) * NG + col) =
                __floats2half2_rn(acc[mb][nb][2], acc[mb][nb][3]);
        }
    }
}

// ---------------- kernel 3: LSTM epilogue (half gates in, fp32 out) ----------------
__device__ __forceinline__ float fast_sigmoid(float x) {
    return __fdividef(1.f, 1.f + __expf(-x));
}
__device__ __forceinline__ float fast_tanh(float x) {
    return __fdividef(2.f, 1.f + __expf(-2.f * x)) - 1.f;
}

__global__ void __launch_bounds__(256) lstm_epilogue(
    const __half* __restrict__ gates, const float* __restrict__ c0,
    const float* __restrict__ bias, float* __restrict__ out) {
    int t = blockIdx.x * blockDim.x + threadIdx.x;    // one 8-elem group along n
    int n = (t & 255) * 8;                            // HID/8 = 256
    int m = t >> 8;
    const __half* gb = gates + (size_t)m * NG;

    uint4 fu = *(const uint4*)(gb + n);
    uint4 iu = *(const uint4*)(gb + HID + n);
    uint4 gu = *(const uint4*)(gb + 2 * HID + n);
    const float4 c40 = ((const float4*)(c0 + (size_t)m * HID + n))[0];
    const float4 c41 = ((const float4*)(c0 + (size_t)m * HID + n))[1];
    const float4 bf0 = ((const float4*)(bias + n))[0];
    const float4 bf1 = ((const float4*)(bias + n))[1];
    const float4 bi0 = ((const float4*)(bias + HID + n))[0];
    const float4 bi1 = ((const float4*)(bias + HID + n))[1];
    const float4 bc0 = ((const float4*)(bias + 2 * HID + n))[0];
    const float4 bc1 = ((const float4*)(bias + 2 * HID + n))[1];

    float fv[8], iv[8], cv[8];
    {
        const __half2* fh = (const __half2*)&fu;
        const __half2* ih = (const __half2*)&iu;
        const __half2* gh = (const __half2*)&gu;
        #pragma unroll
        for (int j = 0; j < 4; j++) {
            float2 a = __half22float2(fh[j]); fv[2 * j] = a.x; fv[2 * j + 1] = a.y;
            float2 b = __half22float2(ih[j]); iv[2 * j] = b.x; iv[2 * j + 1] = b.y;
            float2 c = __half22float2(gh[j]); cv[2 * j] = c.x; cv[2 * j + 1] = c.y;
        }
    }
    const float* bfp = (const float*)&bf0;  // bf0,bf1 contiguous on stack
    float bfa[8] = {bf0.x, bf0.y, bf0.z, bf0.w, bf1.x, bf1.y, bf1.z, bf1.w};
    float bia[8] = {bi0.x, bi0.y, bi0.z, bi0.w, bi1.x, bi1.y, bi1.z, bi1.w};
    float bca[8] = {bc0.x, bc0.y, bc0.z, bc0.w, bc1.x, bc1.y, bc1.z, bc1.w};
    float c0a[8] = {c40.x, c40.y, c40.z, c40.w, c41.x, c41.y, c41.z, c41.w};
    (void)bfp;

    float o[8];
    #pragma unroll
    for (int j = 0; j < 8; j++) {
        float sf = fast_sigmoid(fv[j] + bfa[j]);
        float si = fast_sigmoid(iv[j] + bia[j]);
        o[j] = sf * c0a[j] + si * fast_tanh(cv[j] + bca[j]);
    }
    float4* op = (float4*)(out + (size_t)m * HID + n);
    op[0] = make_float4(o[0], o[1], o[2], o[3]);
    op[1] = make_float4(o[4], o[5], o[6], o[7]);
}

// ---------------- host launch ----------------
extern "C" void kernel_launch(void* const* d_in, const int* in_sizes, int n_in,
                              void* d_out, int out_size) {
    const float* X    = (const float*)d_in[0];
    const float* H0   = (const float*)d_in[1];
    const float* C0   = (const float*)d_in[2];
    const float* W    = (const float*)d_in[3];
    const float* Wh   = (const float*)d_in[4];
    const float* Bias = (const float*)d_in[5];
    float* out = (float*)d_out;

    __half* bt = nullptr;
    __half* ah = nullptr;
    __half* gates = nullptr;
    cudaGetSymbolAddress((void**)&bt, g_BT);
    cudaGetSymbolAddress((void**)&ah, g_AH);
    cudaGetSymbolAddress((void**)&gates, g_gates);

    cudaFuncSetAttribute(lstm_gemm, cudaFuncAttributeMaxDynamicSharedMemorySize, SMEM_TOTAL);

    lstm_pack_bt<<<dim3(KTOT / 32, NG / 128), 256>>>(W, Wh, bt);
    lstm_cvt_ah<<<(BATCH * (KTOT / 8)) / 256, 256>>>(X, H0, ah);
    lstm_gemm<<<dim3(NG / 128, BATCH / 128), 128, SMEM_TOTAL>>>(ah, bt, gates);
    lstm_epilogue<<<(BATCH * HID / 8) / 256, 256>>>(gates, C0, Bias, out);
}

// round 9
// speedup vs baseline: 2.0554x; 1.0500x over previous
#include <cuda_runtime.h>
#include <cuda_fp16.h>
#include <cstdint>

// ---------------- problem constants ----------------
#define BATCH 8192
#define INSZ  1024
#define HID   2048
#define NG    6144            // 3*HID
#define KTOT  3072            // INSZ + HID
#define KITERS 48             // K-chunks of 64 halfs
#define STAGES 3

// Fused CTA tile: 64(M) x 64(N_hid) x 3 gates, 4 warps (2x2), warp tile 32x32/gate
// stage: A 64x64h (8KB) + B 3x64x64h (24KB) = 32KB
#define STAGE_BYTES  32768
#define SMEM_TOTAL (STAGES * STAGE_BYTES)   // 98304 per CTA

// scratch (static device arrays are allowed)
__device__ __half g_BT[(size_t)NG * KTOT];       // [W;Wh]^T K-major, half
__device__ __half g_AH[(size_t)BATCH * KTOT];    // [X|H] merged, half

// ---------------- ptx helpers ----------------
#define CP_ASYNC16(dst, src) \
    asm volatile("cp.async.cg.shared.global [%0], [%1], 16;" :: "r"(dst), "l"(src))
#define CP_COMMIT() asm volatile("cp.async.commit_group;" ::: "memory")
#define CP_WAIT1()  asm volatile("cp.async.wait_group 1;" ::: "memory")

#define LDSM4(r0, r1, r2, r3, addr) \
    asm volatile("ldmatrix.sync.aligned.m8n8.x4.shared.b16 {%0,%1,%2,%3}, [%4];" \
        : "=r"(r0), "=r"(r1), "=r"(r2), "=r"(r3) : "r"(addr))

#define MMA_F16(d, a, b) \
    asm volatile("mma.sync.aligned.m16n8k16.row.col.f32.f16.f16.f32 " \
        "{%0,%1,%2,%3}, {%4,%5,%6,%7}, {%8,%9}, {%0,%1,%2,%3};" \
        : "+f"((d)[0]), "+f"((d)[1]), "+f"((d)[2]), "+f"((d)[3]) \
        : "r"((a)[0]), "r"((a)[1]), "r"((a)[2]), "r"((a)[3]), \
          "r"((b)[0]), "r"((b)[1]))

__device__ __forceinline__ float fast_sigmoid(float x) {
    return __fdividef(1.f, 1.f + __expf(-x));
}
__device__ __forceinline__ float fast_tanh(float x) {
    return __fdividef(2.f, 1.f + __expf(-2.f * x)) - 1.f;
}

// ---------------- kernel 1: pack [W; Wh] -> BT[n][k] (K-major, half) ----------------
__global__ void __launch_bounds__(256) lstm_pack_bt(
    const float* __restrict__ W, const float* __restrict__ Wh, __half* __restrict__ BT) {
    __shared__ float s[32 * 129];
    const int tid = threadIdx.x;
    const int k0 = blockIdx.x * 32, n0 = blockIdx.y * 128;

    #pragma unroll
    for (int i = 0; i < 4; i++) {
        int idx = tid + i * 256;
        int r = idx >> 5;
        int c4 = idx & 31;
        int k = k0 + r;
        const float* src = (k < INSZ) ? (W + (size_t)k * NG + n0 + c4 * 4)
                                      : (Wh + (size_t)(k - INSZ) * NG + n0 + c4 * 4);
        float4 v = *(const float4*)src;
        s[r * 129 + c4 * 4 + 0] = v.x;
        s[r * 129 + c4 * 4 + 1] = v.y;
        s[r * 129 + c4 * 4 + 2] = v.z;
        s[r * 129 + c4 * 4 + 3] = v.w;
    }
    __syncthreads();
    #pragma unroll
    for (int i = 0; i < 4; i++) {
        int idx = tid + i * 256;
        int n = idx >> 3;
        int kg = idx & 7;
        __half2 p0 = __floats2half2_rn(s[(kg * 4 + 0) * 129 + n], s[(kg * 4 + 1) * 129 + n]);
        __half2 p1 = __floats2half2_rn(s[(kg * 4 + 2) * 129 + n], s[(kg * 4 + 3) * 129 + n]);
        uint2 u;
        u.x = *reinterpret_cast<uint32_t*>(&p0);
        u.y = *reinterpret_cast<uint32_t*>(&p1);
        *(uint2*)(BT + (size_t)(n0 + n) * KTOT + k0 + kg * 4) = u;
    }
}

// ---------------- kernel 1b: convert [X|H] -> AH half ----------------
__global__ void __launch_bounds__(256) lstm_cvt_ah(
    const float* __restrict__ X, const float* __restrict__ H, __half* __restrict__ AH) {
    int t = blockIdx.x * blockDim.x + threadIdx.x;
    int m = t / (KTOT / 8);
    int col = (t % (KTOT / 8)) * 8;
    const float* src = (col < INSZ) ? (X + (size_t)m * INSZ + col)
                                    : (H + (size_t)m * HID + (col - INSZ));
    float4 v0 = ((const float4*)src)[0];
    float4 v1 = ((const float4*)src)[1];
    __half2 h0 = __floats2half2_rn(v0.x, v0.y);
    __half2 h1 = __floats2half2_rn(v0.z, v0.w);
    __half2 h2 = __floats2half2_rn(v1.x, v1.y);
    __half2 h3 = __floats2half2_rn(v1.z, v1.w);
    uint4 u;
    u.x = *reinterpret_cast<uint32_t*>(&h0);
    u.y = *reinterpret_cast<uint32_t*>(&h1);
    u.z = *reinterpret_cast<uint32_t*>(&h2);
    u.w = *reinterpret_cast<uint32_t*>(&h3);
    *(uint4*)(AH + (size_t)m * KTOT + col) = u;
}

// ---------------- kernel 2: fused fp16 GEMM (3 gates) + LSTM epilogue ----------------
__global__ void __launch_bounds__(128, 2) lstm_gemm_fused(
    const __half* __restrict__ AH, const __half* __restrict__ BT,
    const float* __restrict__ c0, const float* __restrict__ bias,
    float* __restrict__ out) {
    extern __shared__ char smem[];
    const int tid = threadIdx.x;
    const int lane = tid & 31, wid = tid >> 5;
    const int wm = wid & 1, wn = wid >> 1;            // 2x2 warp grid, 32x32 warp tile/gate
    const int m0 = blockIdx.y * 64, n0 = blockIdx.x * 64;

    const uint32_t sbase = (uint32_t)__cvta_generic_to_shared(smem);

    float acc[3][2][4][4];                            // [gate][mb][nb][4]
    #pragma unroll
    for (int g = 0; g < 3; g++)
        #pragma unroll
        for (int i = 0; i < 2; i++)
            #pragma unroll
            for (int j = 0; j < 4; j++)
                #pragma unroll
                for (int k = 0; k < 4; k++) acc[g][i][j][k] = 0.f;

    const int a_moff = ((lane >> 3) & 1) * 8 + (lane & 7);
    const int a_csel = lane >> 4;
    const int b_noff = ((lane >> 4) & 1) * 8 + (lane & 7);
    const int b_csel = (lane >> 3) & 1;

    // stage: A rows 0..63 (128B each), then B rows 0..191 (gate g at rows g*64..)
    auto load_stage = [&](int kc, int s) {
        const uint32_t As = sbase + s * STAGE_BYTES;
        const uint32_t Bs = As + 8192;
        #pragma unroll
        for (int i = 0; i < 4; i++) {
            int ch = tid + i * 128;                    // 0..511
            int m = ch >> 3, c = ch & 7;
            const __half* src = AH + (size_t)(m0 + m) * KTOT + kc * 64 + c * 8;
            uint32_t dst = As + m * 128 + ((c ^ (m & 7)) << 4);
            CP_ASYNC16(dst, src);
        }
        #pragma unroll
        for (int i = 0; i < 12; i++) {
            int ch = tid + i * 128;                    // 0..1535
            int r = ch >> 3, c = ch & 7;               // r: 0..191
            int g = r >> 6, n = r & 63;
            const __half* src = BT + (size_t)(g * HID + n0 + n) * KTOT + kc * 64 + c * 8;
            uint32_t dst = Bs + r * 128 + ((c ^ (r & 7)) << 4);
            CP_ASYNC16(dst, src);
        }
    };

    auto load_afrag = [&](uint32_t As, int kk, uint32_t a[2][4]) {
        #pragma unroll
        for (int mb = 0; mb < 2; mb++) {
            int m = wm * 32 + mb * 16 + a_moff;
            int c = kk * 2 + a_csel;
            uint32_t addr = As + m * 128 + ((c ^ (m & 7)) << 4);
            LDSM4(a[mb][0], a[mb][1], a[mb][2], a[mb][3], addr);
        }
    };
    auto load_bfrag = [&](uint32_t Bs, int kk, uint32_t b[3][4][2]) {
        #pragma unroll
        for (int g = 0; g < 3; g++) {
            #pragma unroll
            for (int p = 0; p < 2; p++) {
                int r = g * 64 + wn * 32 + p * 16 + b_noff;
                int c = kk * 2 + b_csel;
                uint32_t addr = Bs + r * 128 + ((c ^ (r & 7)) << 4);
                LDSM4(b[g][2 * p][0], b[g][2 * p][1], b[g][2 * p + 1][0], b[g][2 * p + 1][1], addr);
            }
        }
    };

    // prologue: fill 2 of 3 stages
    #pragma unroll
    for (int s = 0; s < STAGES - 1; s++) { load_stage(s, s); CP_COMMIT(); }

    uint32_t afr[2][2][4], bfr[2][3][4][2];

    for (int kc = 0; kc < KITERS; kc++) {
        CP_WAIT1();
        __syncthreads();
        int ls = kc + STAGES - 1;
        if (ls < KITERS) load_stage(ls, ls % STAGES);
        CP_COMMIT();

        const uint32_t As = sbase + (kc % STAGES) * STAGE_BYTES;
        const uint32_t Bs = As + 8192;

        load_afrag(As, 0, afr[0]);
        load_bfrag(Bs, 0, bfr[0]);
        #pragma unroll
        for (int kk = 0; kk < 4; kk++) {
            int cur = kk & 1, nxt = cur ^ 1;
            if (kk < 3) {
                load_afrag(As, kk + 1, afr[nxt]);
                load_bfrag(Bs, kk + 1, bfr[nxt]);
            }
            #pragma unroll
            for (int g = 0; g < 3; g++)
                #pragma unroll
                for (int mb = 0; mb < 2; mb++)
                    #pragma unroll
                    for (int nb = 0; nb < 4; nb++)
                        MMA_F16(acc[g][mb][nb], afr[cur][mb], bfr[cur][g][nb]);
        }
    }

    // ---- fused LSTM epilogue: c1 = sig(f+bf)*c0 + sig(i+bi)*tanh(c+bc) ----
    const int gr = lane >> 2, tig = lane & 3;
    #pragma unroll
    for (int mb = 0; mb < 2; mb++) {
        int row0 = m0 + wm * 32 + mb * 16 + gr;       // rows row0 and row0+8
        #pragma unroll
        for (int nb = 0; nb < 4; nb++) {
            int col = n0 + wn * 32 + nb * 8 + tig * 2;
            float2 bf = *(const float2*)(bias + col);
            float2 bi = *(const float2*)(bias + HID + col);
            float2 bc = *(const float2*)(bias + 2 * HID + col);
            float2 c0a = *(const float2*)(c0 + (size_t)row0 * HID + col);
            float2 c0b = *(const float2*)(c0 + (size_t)(row0 + 8) * HID + col);

            const float* F = acc[0][mb][nb];
            const float* I = acc[1][mb][nb];
            const float* C = acc[2][mb][nb];

            float2 o0, o1;
            o0.x = fast_sigmoid(F[0] + bf.x) * c0a.x +
                   fast_sigmoid(I[0] + bi.x) * fast_tanh(C[0] + bc.x);
            o0.y = fast_sigmoid(F[1] + bf.y) * c0a.y +
                   fast_sigmoid(I[1] + bi.y) * fast_tanh(C[1] + bc.y);
            o1.x = fast_sigmoid(F[2] + bf.x) * c0b.x +
                   fast_sigmoid(I[2] + bi.x) * fast_tanh(C[2] + bc.x);
            o1.y = fast_sigmoid(F[3] + bf.y) * c0b.y +
                   fast_sigmoid(I[3] + bi.y) * fast_tanh(C[3] + bc.y);

            *(float2*)(out + (size_t)row0 * HID + col) = o0;
            *(float2*)(out + (size_t)(row0 + 8) * HID + col) = o1;
        }
    }
}

// ---------------- host launch ----------------
extern "C" void kernel_launch(void* const* d_in, const int* in_sizes, int n_in,
                              void* d_out, int out_size) {
    const float* X    = (const float*)d_in[0];
    const float* H0   = (const float*)d_in[1];
    const float* C0   = (const float*)d_in[2];
    const float* W    = (const float*)d_in[3];
    const float* Wh   = (const float*)d_in[4];
    const float* Bias = (const float*)d_in[5];
    float* out = (float*)d_out;

    __half* bt = nullptr;
    __half* ah = nullptr;
    cudaGetSymbolAddress((void**)&bt, g_BT);
    cudaGetSymbolAddress((void**)&ah, g_AH);

    cudaFuncSetAttribute(lstm_gemm_fused, cudaFuncAttributeMaxDynamicSharedMemorySize,
                         SMEM_TOTAL);

    lstm_pack_bt<<<dim3(KTOT / 32, NG / 128), 256>>>(W, Wh, bt);
    lstm_cvt_ah<<<(BATCH * (KTOT / 8)) / 256, 256>>>(X, H0, ah);
    lstm_gemm_fused<<<dim3(HID / 64, BATCH / 64), 128, SMEM_TOTAL>>>(ah, bt, C0, Bias, out);
}